// round 1
// baseline (speedup 1.0000x reference)
#include <cuda_runtime.h>

#define BATCH   8192
#define DIM     64
#define HID     128
#define NSTEPS  100
#define THREADS 256
#define ROWS_PER_BLK (THREADS / 4)   // 64 rows per block
#define NBLOCKS (BATCH / ROWS_PER_BLK)  // 128

// smem layout (floats)
#define OFF_W1D 0
#define OFF_W2D 8192
#define OFF_W1G 16384
#define OFF_W2G 24576
#define OFF_B1D 32768
#define OFF_B2D 32896
#define OFF_B1G 32960
#define OFF_B2G 33088
#define SMEM_FLOATS 33152

__device__ __forceinline__ float group4_reduce(float v) {
    v += __shfl_xor_sync(0xffffffffu, v, 1);
    v += __shfl_xor_sync(0xffffffffu, v, 2);
    return v;
}

// One MLP: acc[j] += sum_k tanh(x . w1T[k] + b1[k]) * w2[k][j]
// w1 is transposed [HID][DIM] in smem, w2 is [HID][DIM] in smem.
__device__ __forceinline__ void mlp_accum(
    const float* __restrict__ w1, const float* __restrict__ b1,
    const float* __restrict__ w2,
    const float x[16], float acc[16], int sub)
{
    #pragma unroll 4
    for (int k = 0; k < HID; k++) {
        const float4* wv = reinterpret_cast<const float4*>(w1 + k * DIM + sub * 16);
        float p0 = 0.f, p1 = 0.f, p2 = 0.f, p3 = 0.f;
        #pragma unroll
        for (int i = 0; i < 4; i++) {
            float4 w = wv[i];
            p0 = fmaf(x[4*i + 0], w.x, p0);
            p1 = fmaf(x[4*i + 1], w.y, p1);
            p2 = fmaf(x[4*i + 2], w.z, p2);
            p3 = fmaf(x[4*i + 3], w.w, p3);
        }
        float p = group4_reduce((p0 + p1) + (p2 + p3));
        float hk = tanhf(p + b1[k]);
        const float4* uv = reinterpret_cast<const float4*>(w2 + k * DIM + sub * 16);
        #pragma unroll
        for (int i = 0; i < 4; i++) {
            float4 u = uv[i];
            acc[4*i + 0] = fmaf(hk, u.x, acc[4*i + 0]);
            acc[4*i + 1] = fmaf(hk, u.y, acc[4*i + 1]);
            acc[4*i + 2] = fmaf(hk, u.z, acc[4*i + 2]);
            acc[4*i + 3] = fmaf(hk, u.w, acc[4*i + 3]);
        }
    }
}

__global__ void __launch_bounds__(THREADS, 1)
sde_kernel(const float* __restrict__ x0,
           const float* __restrict__ noise,
           const float* __restrict__ Wd1, const float* __restrict__ bd1,
           const float* __restrict__ Wd2, const float* __restrict__ bd2,
           const float* __restrict__ Wg1, const float* __restrict__ bg1,
           const float* __restrict__ Wg2, const float* __restrict__ bg2,
           float* __restrict__ out)
{
    extern __shared__ float sm[];
    float* w1d  = sm + OFF_W1D;
    float* w2d  = sm + OFF_W2D;
    float* w1g  = sm + OFF_W1G;
    float* w2g  = sm + OFF_W2G;
    float* sb1d = sm + OFF_B1D;
    float* sb2d = sm + OFF_B2D;
    float* sb1g = sm + OFF_B1G;
    float* sb2g = sm + OFF_B2G;

    // Stage weights: W1 matrices transposed so column k is contiguous.
    for (int idx = threadIdx.x; idx < DIM * HID; idx += THREADS) {
        int k = idx >> 6;       // 0..127
        int i = idx & 63;       // 0..63
        w1d[idx] = Wd1[i * HID + k];
        w1g[idx] = Wg1[i * HID + k];
        w2d[idx] = Wd2[idx];    // already [HID][DIM]
        w2g[idx] = Wg2[idx];
    }
    for (int idx = threadIdx.x; idx < HID; idx += THREADS) {
        sb1d[idx] = bd1[idx];
        sb1g[idx] = bg1[idx];
    }
    for (int idx = threadIdx.x; idx < DIM; idx += THREADS) {
        sb2d[idx] = bd2[idx];
        sb2g[idx] = bg2[idx];
    }
    __syncthreads();

    const int sub = threadIdx.x & 3;
    const int row = blockIdx.x * ROWS_PER_BLK + (threadIdx.x >> 2);
    const int base = row * DIM + sub * 16;

    float x[16];
    {
        const float4* xin = reinterpret_cast<const float4*>(x0 + base);
        float4* o0 = reinterpret_cast<float4*>(out + base);   // out[0] = x0
        #pragma unroll
        for (int i = 0; i < 4; i++) {
            float4 v = xin[i];
            o0[i] = v;
            x[4*i + 0] = v.x; x[4*i + 1] = v.y;
            x[4*i + 2] = v.z; x[4*i + 3] = v.w;
        }
    }

    // Hoist output-layer bias chunks into registers
    float bd2c[16], bg2c[16];
    #pragma unroll
    for (int j = 0; j < 16; j++) {
        bd2c[j] = sb2d[sub * 16 + j];
        bg2c[j] = sb2g[sub * 16 + j];
    }

    const float DTC = 0.01f;
    const float SDT = 0.1f;   // sqrt(0.01) in fp32

    for (int step = 0; step < NSTEPS; ++step) {
        // noise for this step, pre-scaled by sqrt(dt)
        float nz[16];
        {
            const float4* nv = reinterpret_cast<const float4*>(
                noise + (size_t)step * BATCH * DIM + base);
            #pragma unroll
            for (int i = 0; i < 4; i++) {
                float4 v = nv[i];
                nz[4*i + 0] = v.x * SDT; nz[4*i + 1] = v.y * SDT;
                nz[4*i + 2] = v.z * SDT; nz[4*i + 3] = v.w * SDT;
            }
        }

        // drift MLP:  f = tanh(x@Wd1 + bd1)@Wd2 + bd2
        float acc[16];
        #pragma unroll
        for (int j = 0; j < 16; j++) acc[j] = bd2c[j];
        mlp_accum(w1d, sb1d, w2d, x, acc, sub);
        // acc <- x + f*dt  (partial new x; keep x intact for diffusion MLP)
        #pragma unroll
        for (int j = 0; j < 16; j++) acc[j] = fmaf(acc[j], DTC, x[j]);

        // diffusion MLP:  g = tanh(x@Wg1 + bg1)@Wg2 + bg2
        float g[16];
        #pragma unroll
        for (int j = 0; j < 16; j++) g[j] = bg2c[j];
        mlp_accum(w1g, sb1g, w2g, x, g, sub);

        // x <- (x + f*dt) + g * (dw*sqrt(dt))
        #pragma unroll
        for (int j = 0; j < 16; j++) x[j] = fmaf(g[j], nz[j], acc[j]);

        // store trajectory step+1
        float4* ov = reinterpret_cast<float4*>(
            out + (size_t)(step + 1) * BATCH * DIM + base);
        #pragma unroll
        for (int i = 0; i < 4; i++)
            ov[i] = make_float4(x[4*i], x[4*i+1], x[4*i+2], x[4*i+3]);
    }
}

extern "C" void kernel_launch(void* const* d_in, const int* in_sizes, int n_in,
                              void* d_out, int out_size)
{
    const float* x0    = (const float*)d_in[0];
    // d_in[1] = t_span (unused by the dynamics)
    const float* noise = (const float*)d_in[2];
    const float* Wd1   = (const float*)d_in[3];
    const float* bd1   = (const float*)d_in[4];
    const float* Wd2   = (const float*)d_in[5];
    const float* bd2   = (const float*)d_in[6];
    const float* Wg1   = (const float*)d_in[7];
    const float* bg1   = (const float*)d_in[8];
    const float* Wg2   = (const float*)d_in[9];
    const float* bg2   = (const float*)d_in[10];
    float* out = (float*)d_out;

    size_t smem = SMEM_FLOATS * sizeof(float);   // ~132.6 KB
    cudaFuncSetAttribute(sde_kernel,
                         cudaFuncAttributeMaxDynamicSharedMemorySize, (int)smem);

    sde_kernel<<<NBLOCKS, THREADS, smem>>>(
        x0, noise, Wd1, bd1, Wd2, bd2, Wg1, bg1, Wg2, bg2, out);
}

// round 3
// speedup vs baseline: 9.4539x; 9.4539x over previous
#include <cuda_runtime.h>
#include <cuda_bf16.h>
#include <cstdint>

#define BATCH   8192
#define DIM     64
#define HID     128
#define NSTEPS  100
#define THREADS 128
#define NBLK    128

// ---- smem layout (bytes) ----
#define P1 272u   // W1^T row pitch: 128 bf16 slots (hi k0..63 @2k, lo @128+2k) + 16B pad
#define P2 528u   // W2^T row pitch: 256 bf16 slots (hi k0..127 @2k, lo @256+2k) + 16B pad
#define W1D_OFF 0u
#define W1G_OFF 34816u       // 128*272
#define W2D_OFF 69632u
#define W2G_OFF 103424u      // + 64*528
#define B1D_OFF 137216u
#define B1G_OFF 137728u
#define B2D_OFF 138240u
#define B2G_OFF 138496u
#define SMEM_TOTAL 138752u

__device__ __forceinline__ uint32_t smem_u32(const void* p) {
    uint32_t a;
    asm("{ .reg .u64 t; cvta.to.shared.u64 t, %1; cvt.u32.u64 %0, t; }"
        : "=r"(a) : "l"(p));
    return a;
}

__device__ __forceinline__ void mma_bf16(float* c, const uint32_t* a,
                                         uint32_t b0, uint32_t b1) {
    asm volatile(
        "mma.sync.aligned.m16n8k16.row.col.f32.bf16.bf16.f32 "
        "{%0,%1,%2,%3}, {%4,%5,%6,%7}, {%8,%9}, {%0,%1,%2,%3};"
        : "+f"(c[0]), "+f"(c[1]), "+f"(c[2]), "+f"(c[3])
        : "r"(a[0]), "r"(a[1]), "r"(a[2]), "r"(a[3]), "r"(b0), "r"(b1));
}

__device__ __forceinline__ void ldsm4(uint32_t* r, uint32_t addr) {
    asm volatile("ldmatrix.sync.aligned.m8n8.x4.shared.b16 {%0,%1,%2,%3}, [%4];"
                 : "=r"(r[0]), "=r"(r[1]), "=r"(r[2]), "=r"(r[3]) : "r"(addr));
}

// pack (lo element, hi element) -> bf16x2
__device__ __forceinline__ uint32_t packbf(float lo, float hi) {
    uint32_t r;
    asm("cvt.rn.bf16x2.f32 %0, %1, %2;" : "=r"(r) : "f"(hi), "f"(lo));
    return r;
}
// residual pair packed: v - f32(bf16(v))
__device__ __forceinline__ uint32_t resid(uint32_t hpack, float v0, float v1) {
    float h0 = __uint_as_float(hpack << 16);
    float h1 = __uint_as_float(hpack & 0xffff0000u);
    return packbf(v0 - h0, v1 - h1);
}

// GEMM1: acc[16 n-tiles][4] += X[16,64] @ W1 (split 3-term), B from smem pitch P1
__device__ __forceinline__ void gemm1(float (&acc)[16][4],
    const uint32_t (&xh)[4][4], const uint32_t (&xl)[4][4], uint32_t base)
{
    #pragma unroll
    for (int kk = 0; kk < 4; kk++) {
        #pragma unroll
        for (int t2 = 0; t2 < 8; t2++) {
            uint32_t addr = base + (uint32_t)t2 * (16u * P1) + (uint32_t)kk * 32u;
            uint32_t bh[4]; ldsm4(bh, addr);
            mma_bf16(acc[2*t2],   xh[kk], bh[0], bh[1]);
            mma_bf16(acc[2*t2+1], xh[kk], bh[2], bh[3]);
            mma_bf16(acc[2*t2],   xl[kk], bh[0], bh[1]);
            mma_bf16(acc[2*t2+1], xl[kk], bh[2], bh[3]);
            uint32_t bl[4]; ldsm4(bl, addr + 128u);
            mma_bf16(acc[2*t2],   xh[kk], bl[0], bl[1]);
            mma_bf16(acc[2*t2+1], xh[kk], bl[2], bl[3]);
        }
    }
}

// GEMM2: acc[8 n-tiles][4] += H[16,128] @ W2 (split 3-term), B from smem pitch P2
__device__ __forceinline__ void gemm2(float (&acc)[8][4],
    const uint32_t (&Hh)[16][2], const uint32_t (&Hl)[16][2], uint32_t base)
{
    #pragma unroll
    for (int kk = 0; kk < 8; kk++) {
        uint32_t ah[4] = {Hh[2*kk][0], Hh[2*kk][1], Hh[2*kk+1][0], Hh[2*kk+1][1]};
        uint32_t al[4] = {Hl[2*kk][0], Hl[2*kk][1], Hl[2*kk+1][0], Hl[2*kk+1][1]};
        #pragma unroll
        for (int g2 = 0; g2 < 4; g2++) {
            uint32_t addr = base + (uint32_t)g2 * (16u * P2) + (uint32_t)kk * 32u;
            uint32_t bh[4]; ldsm4(bh, addr);
            mma_bf16(acc[2*g2],   ah, bh[0], bh[1]);
            mma_bf16(acc[2*g2+1], ah, bh[2], bh[3]);
            mma_bf16(acc[2*g2],   al, bh[0], bh[1]);
            mma_bf16(acc[2*g2+1], al, bh[2], bh[3]);
            uint32_t bl[4]; ldsm4(bl, addr + 256u);
            mma_bf16(acc[2*g2],   ah, bl[0], bl[1]);
            mma_bf16(acc[2*g2+1], ah, bl[2], bl[3]);
        }
    }
}

__device__ __forceinline__ void tanh_pack(const float (&acc)[16][4],
    const float* bias_sm, int cpair, uint32_t (&Hh)[16][2], uint32_t (&Hl)[16][2])
{
    #pragma unroll
    for (int t = 0; t < 16; t++) {
        float b0 = bias_sm[8*t + cpair];
        float b1 = bias_sm[8*t + cpair + 1];
        float h0 = tanhf(acc[t][0] + b0);
        float h1 = tanhf(acc[t][1] + b1);
        float h2 = tanhf(acc[t][2] + b0);
        float h3 = tanhf(acc[t][3] + b1);
        Hh[t][0] = packbf(h0, h1);
        Hl[t][0] = resid(Hh[t][0], h0, h1);
        Hh[t][1] = packbf(h2, h3);
        Hl[t][1] = resid(Hh[t][1], h2, h3);
    }
}

__global__ void __launch_bounds__(THREADS, 1)
sde_mma_kernel(const float* __restrict__ x0,
               const float* __restrict__ noise,
               const float* __restrict__ Wd1, const float* __restrict__ bd1,
               const float* __restrict__ Wd2, const float* __restrict__ bd2,
               const float* __restrict__ Wg1, const float* __restrict__ bg1,
               const float* __restrict__ Wg2, const float* __restrict__ bg2,
               float* __restrict__ out)
{
    extern __shared__ char smc[];
    const uint32_t smem_base = smem_u32(smc);
    const int tid = threadIdx.x;

    // ---- stage weights (hi/lo bf16 split, transposed [n][k], padded pitch) ----
    for (int idx = tid; idx < DIM * HID; idx += THREADS) {     // W1: [64 k][128 n]
        int k = idx >> 7, n = idx & 127;
        float wd = Wd1[idx], wg = Wg1[idx];
        __nv_bfloat16 hd = __float2bfloat16(wd);
        __nv_bfloat16 hg = __float2bfloat16(wg);
        __nv_bfloat16 ldv = __float2bfloat16(wd - __bfloat162float(hd));
        __nv_bfloat16 lgv = __float2bfloat16(wg - __bfloat162float(hg));
        char* rowd = smc + W1D_OFF + (uint32_t)n * P1;
        char* rowg = smc + W1G_OFF + (uint32_t)n * P1;
        *(__nv_bfloat16*)(rowd + 2*k)       = hd;
        *(__nv_bfloat16*)(rowd + 128 + 2*k) = ldv;
        *(__nv_bfloat16*)(rowg + 2*k)       = hg;
        *(__nv_bfloat16*)(rowg + 128 + 2*k) = lgv;
    }
    for (int idx = tid; idx < HID * DIM; idx += THREADS) {     // W2: [128 k][64 n]
        int k = idx >> 6, n = idx & 63;
        float wd = Wd2[idx], wg = Wg2[idx];
        __nv_bfloat16 hd = __float2bfloat16(wd);
        __nv_bfloat16 hg = __float2bfloat16(wg);
        __nv_bfloat16 ldv = __float2bfloat16(wd - __bfloat162float(hd));
        __nv_bfloat16 lgv = __float2bfloat16(wg - __bfloat162float(hg));
        char* rowd = smc + W2D_OFF + (uint32_t)n * P2;
        char* rowg = smc + W2G_OFF + (uint32_t)n * P2;
        *(__nv_bfloat16*)(rowd + 2*k)       = hd;
        *(__nv_bfloat16*)(rowd + 256 + 2*k) = ldv;
        *(__nv_bfloat16*)(rowg + 2*k)       = hg;
        *(__nv_bfloat16*)(rowg + 256 + 2*k) = lgv;
    }
    for (int i = tid; i < HID; i += THREADS) {
        ((float*)(smc + B1D_OFF))[i] = bd1[i];
        ((float*)(smc + B1G_OFF))[i] = bg1[i];
    }
    for (int i = tid; i < DIM; i += THREADS) {
        ((float*)(smc + B2D_OFF))[i] = bd2[i];
        ((float*)(smc + B2G_OFF))[i] = bg2[i];
    }
    __syncthreads();

    const int wid = tid >> 5, lane = tid & 31;
    const int g = lane >> 2;              // fragment row group
    const int cpair = (lane & 3) * 2;     // fragment col pair
    const int row0 = (blockIdx.x * 4 + wid) * 16 + g;   // rows row0 and row0+8

    // ldmatrix per-lane base address components
    const int rowA = (lane & 7) + ((lane >> 4) << 3);
    const uint32_t colo = (uint32_t)((lane >> 3) & 1) * 16u;
    const uint32_t g1d = smem_base + W1D_OFF + (uint32_t)rowA * P1 + colo;
    const uint32_t g1g = smem_base + W1G_OFF + (uint32_t)rowA * P1 + colo;
    const uint32_t g2d = smem_base + W2D_OFF + (uint32_t)rowA * P2 + colo;
    const uint32_t g2g = smem_base + W2G_OFF + (uint32_t)rowA * P2 + colo;

    const float* sb1d = (const float*)(smc + B1D_OFF);
    const float* sb1g = (const float*)(smc + B1G_OFF);
    const float* sb2d = (const float*)(smc + B2D_OFF);
    const float* sb2g = (const float*)(smc + B2G_OFF);

    // x state in C-fragment layout: 8 tiles x 4 floats
    float x[8][4];
    #pragma unroll
    for (int t = 0; t < 8; t++) {
        const float* p0 = x0 + (size_t)row0 * DIM + 8*t + cpair;
        const float* p1 = x0 + (size_t)(row0 + 8) * DIM + 8*t + cpair;
        float2 v0 = *(const float2*)p0;
        float2 v1 = *(const float2*)p1;
        x[t][0] = v0.x; x[t][1] = v0.y; x[t][2] = v1.x; x[t][3] = v1.y;
        *(float2*)(out + (size_t)row0 * DIM + 8*t + cpair) = v0;
        *(float2*)(out + (size_t)(row0 + 8) * DIM + 8*t + cpair) = v1;
    }

    const float DTC = 0.01f;
    const float SDT = 0.1f;

    #pragma unroll 1
    for (int step = 0; step < NSTEPS; ++step) {
        // ---- x A-fragments (hi/lo split), shared by both MLPs ----
        uint32_t xh[4][4], xl[4][4];
        #pragma unroll
        for (int kk = 0; kk < 4; kk++) {
            xh[kk][0] = packbf(x[2*kk][0],   x[2*kk][1]);
            xl[kk][0] = resid (xh[kk][0], x[2*kk][0],   x[2*kk][1]);
            xh[kk][1] = packbf(x[2*kk][2],   x[2*kk][3]);
            xl[kk][1] = resid (xh[kk][1], x[2*kk][2],   x[2*kk][3]);
            xh[kk][2] = packbf(x[2*kk+1][0], x[2*kk+1][1]);
            xl[kk][2] = resid (xh[kk][2], x[2*kk+1][0], x[2*kk+1][1]);
            xh[kk][3] = packbf(x[2*kk+1][2], x[2*kk+1][3]);
            xl[kk][3] = resid (xh[kk][3], x[2*kk+1][2], x[2*kk+1][3]);
        }

        uint32_t Hh[16][2], Hl[16][2];

        // ---- drift MLP ----
        float acc1[16][4];
        #pragma unroll
        for (int t = 0; t < 16; t++) { acc1[t][0]=0.f; acc1[t][1]=0.f; acc1[t][2]=0.f; acc1[t][3]=0.f; }
        gemm1(acc1, xh, xl, g1d);
        tanh_pack(acc1, sb1d, cpair, Hh, Hl);

        float facc[8][4];
        #pragma unroll
        for (int t = 0; t < 8; t++) { facc[t][0]=0.f; facc[t][1]=0.f; facc[t][2]=0.f; facc[t][3]=0.f; }
        gemm2(facc, Hh, Hl, g2d);

        // ---- diffusion MLP ----
        float acc1g[16][4];
        #pragma unroll
        for (int t = 0; t < 16; t++) { acc1g[t][0]=0.f; acc1g[t][1]=0.f; acc1g[t][2]=0.f; acc1g[t][3]=0.f; }
        gemm1(acc1g, xh, xl, g1g);
        tanh_pack(acc1g, sb1g, cpair, Hh, Hl);

        // noise (pre-scaled), loaded here so LDG overlaps GEMM2g
        float nz[8][4];
        {
            const float* nb = noise + (size_t)step * BATCH * DIM;
            #pragma unroll
            for (int t = 0; t < 8; t++) {
                float2 v0 = *(const float2*)(nb + (size_t)row0 * DIM + 8*t + cpair);
                float2 v1 = *(const float2*)(nb + (size_t)(row0 + 8) * DIM + 8*t + cpair);
                nz[t][0] = v0.x * SDT; nz[t][1] = v0.y * SDT;
                nz[t][2] = v1.x * SDT; nz[t][3] = v1.y * SDT;
            }
        }

        float gacc[8][4];
        #pragma unroll
        for (int t = 0; t < 8; t++) { gacc[t][0]=0.f; gacc[t][1]=0.f; gacc[t][2]=0.f; gacc[t][3]=0.f; }
        gemm2(gacc, Hh, Hl, g2g);

        // ---- Euler–Maruyama update + store ----
        float* ob = out + (size_t)(step + 1) * BATCH * DIM;
        #pragma unroll
        for (int t = 0; t < 8; t++) {
            float bd0 = sb2d[8*t + cpair], bd1v = sb2d[8*t + cpair + 1];
            float bg0 = sb2g[8*t + cpair], bg1v = sb2g[8*t + cpair + 1];
            x[t][0] = fmaf(gacc[t][0] + bg0,  nz[t][0], fmaf(facc[t][0] + bd0,  DTC, x[t][0]));
            x[t][1] = fmaf(gacc[t][1] + bg1v, nz[t][1], fmaf(facc[t][1] + bd1v, DTC, x[t][1]));
            x[t][2] = fmaf(gacc[t][2] + bg0,  nz[t][2], fmaf(facc[t][2] + bd0,  DTC, x[t][2]));
            x[t][3] = fmaf(gacc[t][3] + bg1v, nz[t][3], fmaf(facc[t][3] + bd1v, DTC, x[t][3]));
            *(float2*)(ob + (size_t)row0 * DIM + 8*t + cpair)       = make_float2(x[t][0], x[t][1]);
            *(float2*)(ob + (size_t)(row0 + 8) * DIM + 8*t + cpair) = make_float2(x[t][2], x[t][3]);
        }
    }
}

extern "C" void kernel_launch(void* const* d_in, const int* in_sizes, int n_in,
                              void* d_out, int out_size)
{
    const float* x0    = (const float*)d_in[0];
    const float* noise = (const float*)d_in[2];
    const float* Wd1   = (const float*)d_in[3];
    const float* bd1   = (const float*)d_in[4];
    const float* Wd2   = (const float*)d_in[5];
    const float* bd2   = (const float*)d_in[6];
    const float* Wg1   = (const float*)d_in[7];
    const float* bg1   = (const float*)d_in[8];
    const float* Wg2   = (const float*)d_in[9];
    const float* bg2   = (const float*)d_in[10];
    float* out = (float*)d_out;

    cudaFuncSetAttribute(sde_mma_kernel,
                         cudaFuncAttributeMaxDynamicSharedMemorySize, SMEM_TOTAL);
    sde_mma_kernel<<<NBLK, THREADS, SMEM_TOTAL>>>(
        x0, noise, Wd1, bd1, Wd2, bd2, Wg1, bg1, Wg2, bg2, out);
}

// round 4
// speedup vs baseline: 13.5609x; 1.4344x over previous
#include <cuda_runtime.h>
#include <cuda_bf16.h>
#include <cstdint>

#define BATCH   8192
#define DIM     64
#define HID     128
#define NSTEPS  100
#define THREADS 256
#define NBLK    128

// ---- smem layout (bytes) ----
#define P1 272u   // W1^T row pitch: hi k0..63 @2k, lo @128+2k, +16B pad
#define P2 528u   // W2^T row pitch: hi k0..127 @2k, lo @256+2k, +16B pad
#define W1D_OFF 0u
#define W1G_OFF 34816u       // 128*272
#define W2D_OFF 69632u
#define W2G_OFF 103424u
#define B1D_OFF 137216u
#define B1G_OFF 137728u
#define B2D_OFF 138240u
#define B2G_OFF 138496u
#define XFRAG_OFF 138752u    // [4 tiles][2 kinds][4 kk][32 lanes][16B] = 16KB
#define GEX_OFF   155136u    // [4 tiles][8 t][32 lanes][16B] = 16KB
#define SMEM_TOTAL 171520u

__device__ __forceinline__ uint32_t smem_u32(const void* p) {
    uint32_t a;
    asm("{ .reg .u64 t; cvta.to.shared.u64 t, %1; cvt.u32.u64 %0, t; }"
        : "=r"(a) : "l"(p));
    return a;
}

__device__ __forceinline__ void mma_bf16(float* c, const uint32_t* a,
                                         uint32_t b0, uint32_t b1) {
    asm volatile(
        "mma.sync.aligned.m16n8k16.row.col.f32.bf16.bf16.f32 "
        "{%0,%1,%2,%3}, {%4,%5,%6,%7}, {%8,%9}, {%0,%1,%2,%3};"
        : "+f"(c[0]), "+f"(c[1]), "+f"(c[2]), "+f"(c[3])
        : "r"(a[0]), "r"(a[1]), "r"(a[2]), "r"(a[3]), "r"(b0), "r"(b1));
}

__device__ __forceinline__ void ldsm4(uint32_t* r, uint32_t addr) {
    asm volatile("ldmatrix.sync.aligned.m8n8.x4.shared.b16 {%0,%1,%2,%3}, [%4];"
                 : "=r"(r[0]), "=r"(r[1]), "=r"(r[2]), "=r"(r[3]) : "r"(addr));
}

__device__ __forceinline__ uint32_t packbf(float lo, float hi) {
    uint32_t r;
    asm("cvt.rn.bf16x2.f32 %0, %1, %2;" : "=r"(r) : "f"(hi), "f"(lo));
    return r;
}
__device__ __forceinline__ uint32_t resid(uint32_t hpack, float v0, float v1) {
    float h0 = __uint_as_float(hpack << 16);
    float h1 = __uint_as_float(hpack & 0xffff0000u);
    return packbf(v0 - h0, v1 - h1);
}

// GEMM1: acc[16][4] += X[16,64] @ W1 (3-term split)
__device__ __forceinline__ void gemm1(float (&acc)[16][4],
    const uint32_t (&xh)[4][4], const uint32_t (&xl)[4][4], uint32_t base)
{
    #pragma unroll
    for (int kk = 0; kk < 4; kk++) {
        #pragma unroll
        for (int t2 = 0; t2 < 8; t2++) {
            uint32_t addr = base + (uint32_t)t2 * (16u * P1) + (uint32_t)kk * 32u;
            uint32_t bh[4]; ldsm4(bh, addr);
            mma_bf16(acc[2*t2],   xh[kk], bh[0], bh[1]);
            mma_bf16(acc[2*t2+1], xh[kk], bh[2], bh[3]);
            mma_bf16(acc[2*t2],   xl[kk], bh[0], bh[1]);
            mma_bf16(acc[2*t2+1], xl[kk], bh[2], bh[3]);
            uint32_t bl[4]; ldsm4(bl, addr + 128u);
            mma_bf16(acc[2*t2],   xh[kk], bl[0], bl[1]);
            mma_bf16(acc[2*t2+1], xh[kk], bl[2], bl[3]);
        }
    }
}

// GEMM2: acc[8][4] += H[16,128] @ W2 (3-term split)
__device__ __forceinline__ void gemm2(float (&acc)[8][4],
    const uint32_t (&Hh)[16][2], const uint32_t (&Hl)[16][2], uint32_t base)
{
    #pragma unroll
    for (int kk = 0; kk < 8; kk++) {
        uint32_t ah[4] = {Hh[2*kk][0], Hh[2*kk][1], Hh[2*kk+1][0], Hh[2*kk+1][1]};
        uint32_t al[4] = {Hl[2*kk][0], Hl[2*kk][1], Hl[2*kk+1][0], Hl[2*kk+1][1]};
        #pragma unroll
        for (int g2 = 0; g2 < 4; g2++) {
            uint32_t addr = base + (uint32_t)g2 * (16u * P2) + (uint32_t)kk * 32u;
            uint32_t bh[4]; ldsm4(bh, addr);
            mma_bf16(acc[2*g2],   ah, bh[0], bh[1]);
            mma_bf16(acc[2*g2+1], ah, bh[2], bh[3]);
            mma_bf16(acc[2*g2],   al, bh[0], bh[1]);
            mma_bf16(acc[2*g2+1], al, bh[2], bh[3]);
            uint32_t bl[4]; ldsm4(bl, addr + 256u);
            mma_bf16(acc[2*g2],   ah, bl[0], bl[1]);
            mma_bf16(acc[2*g2+1], ah, bl[2], bl[3]);
        }
    }
}

__device__ __forceinline__ void tanh_pack(const float (&acc)[16][4],
    const float* bias_sm, int cpair, uint32_t (&Hh)[16][2], uint32_t (&Hl)[16][2])
{
    #pragma unroll
    for (int t = 0; t < 16; t++) {
        float b0 = bias_sm[8*t + cpair];
        float b1 = bias_sm[8*t + cpair + 1];
        float h0 = tanhf(acc[t][0] + b0);
        float h1 = tanhf(acc[t][1] + b1);
        float h2 = tanhf(acc[t][2] + b0);
        float h3 = tanhf(acc[t][3] + b1);
        Hh[t][0] = packbf(h0, h1);
        Hl[t][0] = resid(Hh[t][0], h0, h1);
        Hh[t][1] = packbf(h2, h3);
        Hl[t][1] = resid(Hh[t][1], h2, h3);
    }
}

__device__ __forceinline__ void pack_frags(const float (&x)[8][4],
    uint32_t (&xh)[4][4], uint32_t (&xl)[4][4])
{
    #pragma unroll
    for (int kk = 0; kk < 4; kk++) {
        xh[kk][0] = packbf(x[2*kk][0],   x[2*kk][1]);
        xl[kk][0] = resid (xh[kk][0], x[2*kk][0],   x[2*kk][1]);
        xh[kk][1] = packbf(x[2*kk][2],   x[2*kk][3]);
        xl[kk][1] = resid (xh[kk][1], x[2*kk][2],   x[2*kk][3]);
        xh[kk][2] = packbf(x[2*kk+1][0], x[2*kk+1][1]);
        xl[kk][2] = resid (xh[kk][2], x[2*kk+1][0], x[2*kk+1][1]);
        xh[kk][3] = packbf(x[2*kk+1][2], x[2*kk+1][3]);
        xl[kk][3] = resid (xh[kk][3], x[2*kk+1][2], x[2*kk+1][3]);
    }
}

__global__ void __launch_bounds__(THREADS, 1)
sde_ws_kernel(const float* __restrict__ x0,
              const float* __restrict__ noise,
              const float* __restrict__ Wd1, const float* __restrict__ bd1,
              const float* __restrict__ Wd2, const float* __restrict__ bd2,
              const float* __restrict__ Wg1, const float* __restrict__ bg1,
              const float* __restrict__ Wg2, const float* __restrict__ bg2,
              float* __restrict__ out)
{
    extern __shared__ char smc[];
    const uint32_t smem_base = smem_u32(smc);
    const int tid = threadIdx.x;

    // ---- stage weights (hi/lo bf16 split, transposed [n][k], padded pitch) ----
    for (int idx = tid; idx < DIM * HID; idx += THREADS) {     // W1: [64 k][128 n]
        int k = idx >> 7, n = idx & 127;
        float wd = Wd1[idx], wg = Wg1[idx];
        __nv_bfloat16 hd = __float2bfloat16(wd);
        __nv_bfloat16 hg = __float2bfloat16(wg);
        __nv_bfloat16 ldv = __float2bfloat16(wd - __bfloat162float(hd));
        __nv_bfloat16 lgv = __float2bfloat16(wg - __bfloat162float(hg));
        char* rowd = smc + W1D_OFF + (uint32_t)n * P1;
        char* rowg = smc + W1G_OFF + (uint32_t)n * P1;
        *(__nv_bfloat16*)(rowd + 2*k)       = hd;
        *(__nv_bfloat16*)(rowd + 128 + 2*k) = ldv;
        *(__nv_bfloat16*)(rowg + 2*k)       = hg;
        *(__nv_bfloat16*)(rowg + 128 + 2*k) = lgv;
    }
    for (int idx = tid; idx < HID * DIM; idx += THREADS) {     // W2: [128 k][64 n]
        int k = idx >> 6, n = idx & 63;
        float wd = Wd2[idx], wg = Wg2[idx];
        __nv_bfloat16 hd = __float2bfloat16(wd);
        __nv_bfloat16 hg = __float2bfloat16(wg);
        __nv_bfloat16 ldv = __float2bfloat16(wd - __bfloat162float(hd));
        __nv_bfloat16 lgv = __float2bfloat16(wg - __bfloat162float(hg));
        char* rowd = smc + W2D_OFF + (uint32_t)n * P2;
        char* rowg = smc + W2G_OFF + (uint32_t)n * P2;
        *(__nv_bfloat16*)(rowd + 2*k)       = hd;
        *(__nv_bfloat16*)(rowd + 256 + 2*k) = ldv;
        *(__nv_bfloat16*)(rowg + 2*k)       = hg;
        *(__nv_bfloat16*)(rowg + 256 + 2*k) = lgv;
    }
    for (int i = tid; i < HID; i += THREADS) {
        ((float*)(smc + B1D_OFF))[i] = bd1[i];
        ((float*)(smc + B1G_OFF))[i] = bg1[i];
    }
    for (int i = tid; i < DIM; i += THREADS) {
        ((float*)(smc + B2D_OFF))[i] = bd2[i];
        ((float*)(smc + B2G_OFF))[i] = bg2[i];
    }
    __syncthreads();

    const int wid  = tid >> 5, lane = tid & 31;
    const int tile = wid & 3;              // warp pair (tile, tile+4) on SMSP 'tile'
    const bool isF = (wid < 4);            // drift/update warp vs diffusion warp
    const int g = lane >> 2;
    const int cpair = (lane & 3) * 2;
    const int row0 = blockIdx.x * 64 + tile * 16 + g;
    const int barid = 1 + tile;

    // ldmatrix per-lane base address components
    const int rowA = (lane & 7) + ((lane >> 4) << 3);
    const uint32_t colo = (uint32_t)((lane >> 3) & 1) * 16u;
    const uint32_t g1 = smem_base + (isF ? W1D_OFF : W1G_OFF) + (uint32_t)rowA * P1 + colo;
    const uint32_t g2 = smem_base + (isF ? W2D_OFF : W2G_OFF) + (uint32_t)rowA * P2 + colo;

    const float* sb1  = (const float*)(smc + (isF ? B1D_OFF : B1G_OFF));
    const float* sb2d = (const float*)(smc + B2D_OFF);
    const float* sb2g = (const float*)(smc + B2G_OFF);

    // exchange buffers (lane-to-lane, conflict-free 16B/lane)
    char* xfp = smc + XFRAG_OFF + (uint32_t)tile * 4096u + (uint32_t)lane * 16u;
    char* gxp = smc + GEX_OFF   + (uint32_t)tile * 4096u + (uint32_t)lane * 16u;

    // ---- init: both warps load x0 and pack fragments; f-warp keeps x + writes out[0]
    float x[8][4];
    uint32_t xh[4][4], xl[4][4];
    #pragma unroll
    for (int t = 0; t < 8; t++) {
        float2 v0 = *(const float2*)(x0 + (size_t)row0 * DIM + 8*t + cpair);
        float2 v1 = *(const float2*)(x0 + (size_t)(row0 + 8) * DIM + 8*t + cpair);
        x[t][0] = v0.x; x[t][1] = v0.y; x[t][2] = v1.x; x[t][3] = v1.y;
        if (isF) {
            *(float2*)(out + (size_t)row0 * DIM + 8*t + cpair) = v0;
            *(float2*)(out + (size_t)(row0 + 8) * DIM + 8*t + cpair) = v1;
        }
    }
    pack_frags(x, xh, xl);

    const float DTC = 0.01f;
    const float SDT = 0.1f;

    #pragma unroll 1
    for (int step = 0; step < NSTEPS; ++step) {
        float nz[8][4];
        if (isF) {   // prefetch noise early so LDG overlaps the GEMMs
            const float* nb = noise + (size_t)step * BATCH * DIM;
            #pragma unroll
            for (int t = 0; t < 8; t++) {
                float2 v0 = *(const float2*)(nb + (size_t)row0 * DIM + 8*t + cpair);
                float2 v1 = *(const float2*)(nb + (size_t)(row0 + 8) * DIM + 8*t + cpair);
                nz[t][0] = v0.x * SDT; nz[t][1] = v0.y * SDT;
                nz[t][2] = v1.x * SDT; nz[t][3] = v1.y * SDT;
            }
        }

        // ---- own MLP: GEMM1 -> tanh -> GEMM2 ----
        float acc1[16][4];
        #pragma unroll
        for (int t = 0; t < 16; t++) { acc1[t][0]=0.f; acc1[t][1]=0.f; acc1[t][2]=0.f; acc1[t][3]=0.f; }
        gemm1(acc1, xh, xl, g1);

        uint32_t Hh[16][2], Hl[16][2];
        tanh_pack(acc1, sb1, cpair, Hh, Hl);

        float a2[8][4];
        #pragma unroll
        for (int t = 0; t < 8; t++) { a2[t][0]=0.f; a2[t][1]=0.f; a2[t][2]=0.f; a2[t][3]=0.f; }
        gemm2(a2, Hh, Hl, g2);

        if (!isF) {
            // diffusion warp: publish g (+bias), then fetch next-step x frags
            #pragma unroll
            for (int t = 0; t < 8; t++) {
                float b0 = sb2g[8*t + cpair], b1 = sb2g[8*t + cpair + 1];
                float4 v = make_float4(a2[t][0] + b0, a2[t][1] + b1,
                                       a2[t][2] + b0, a2[t][3] + b1);
                *(float4*)(gxp + t * 512) = v;
            }
            asm volatile("bar.sync %0, %1;" :: "r"(barid), "n"(64) : "memory");
            asm volatile("bar.sync %0, %1;" :: "r"(barid), "n"(64) : "memory");
            #pragma unroll
            for (int kk = 0; kk < 4; kk++) {
                uint4 vh = *(uint4*)(xfp + kk * 512);
                uint4 vl = *(uint4*)(xfp + 2048 + kk * 512);
                xh[kk][0] = vh.x; xh[kk][1] = vh.y; xh[kk][2] = vh.z; xh[kk][3] = vh.w;
                xl[kk][0] = vl.x; xl[kk][1] = vl.y; xl[kk][2] = vl.z; xl[kk][3] = vl.w;
            }
        } else {
            // drift warp: wait for g, do Euler-Maruyama update, publish new x frags
            asm volatile("bar.sync %0, %1;" :: "r"(barid), "n"(64) : "memory");
            float* ob = out + (size_t)(step + 1) * BATCH * DIM;
            #pragma unroll
            for (int t = 0; t < 8; t++) {
                float4 gv = *(const float4*)(gxp + t * 512);
                float bd0 = sb2d[8*t + cpair], bd1v = sb2d[8*t + cpair + 1];
                x[t][0] = fmaf(gv.x, nz[t][0], fmaf(a2[t][0] + bd0,  DTC, x[t][0]));
                x[t][1] = fmaf(gv.y, nz[t][1], fmaf(a2[t][1] + bd1v, DTC, x[t][1]));
                x[t][2] = fmaf(gv.z, nz[t][2], fmaf(a2[t][2] + bd0,  DTC, x[t][2]));
                x[t][3] = fmaf(gv.w, nz[t][3], fmaf(a2[t][3] + bd1v, DTC, x[t][3]));
                *(float2*)(ob + (size_t)row0 * DIM + 8*t + cpair)       = make_float2(x[t][0], x[t][1]);
                *(float2*)(ob + (size_t)(row0 + 8) * DIM + 8*t + cpair) = make_float2(x[t][2], x[t][3]);
            }
            pack_frags(x, xh, xl);
            #pragma unroll
            for (int kk = 0; kk < 4; kk++) {
                *(uint4*)(xfp + kk * 512)        = make_uint4(xh[kk][0], xh[kk][1], xh[kk][2], xh[kk][3]);
                *(uint4*)(xfp + 2048 + kk * 512) = make_uint4(xl[kk][0], xl[kk][1], xl[kk][2], xl[kk][3]);
            }
            asm volatile("bar.sync %0, %1;" :: "r"(barid), "n"(64) : "memory");
        }
    }
}

extern "C" void kernel_launch(void* const* d_in, const int* in_sizes, int n_in,
                              void* d_out, int out_size)
{
    const float* x0    = (const float*)d_in[0];
    const float* noise = (const float*)d_in[2];
    const float* Wd1   = (const float*)d_in[3];
    const float* bd1   = (const float*)d_in[4];
    const float* Wd2   = (const float*)d_in[5];
    const float* bd2   = (const float*)d_in[6];
    const float* Wg1   = (const float*)d_in[7];
    const float* bg1   = (const float*)d_in[8];
    const float* Wg2   = (const float*)d_in[9];
    const float* bg2   = (const float*)d_in[10];
    float* out = (float*)d_out;

    cudaFuncSetAttribute(sde_ws_kernel,
                         cudaFuncAttributeMaxDynamicSharedMemorySize, SMEM_TOTAL);
    sde_ws_kernel<<<NBLK, THREADS, SMEM_TOTAL>>>(
        x0, noise, Wd1, bd1, Wd2, bd2, Wg1, bg1, Wg2, bg2, out);
}

// round 6
// speedup vs baseline: 23.5216x; 1.7345x over previous
#include <cuda_runtime.h>
#include <cuda_fp16.h>
#include <cstdint>

#define BATCH   8192
#define DIM     64
#define HID     128
#define NSTEPS  100
#define THREADS 256
#define NBLK    128

// ---- smem layout (bytes) ----
#define P1 144u   // W1^T row pitch: 64 fp16 = 128B + 16B pad
#define P2 272u   // W2^T row pitch: 128 fp16 = 256B + 16B pad
#define W1D_OFF 0u
#define W1G_OFF 18432u       // 128*144
#define W2D_OFF 36864u
#define W2G_OFF 54272u       // + 64*272
#define B1D_OFF 71680u
#define B1G_OFF 72192u
#define B2D_OFF 72704u
#define B2G_OFF 72960u
#define XFRAG_OFF 73216u     // [4 tiles][4 kk][32 lanes][16B] = 8KB
#define GEX_OFF   81408u     // [4 tiles][8 t][32 lanes][16B] = 16KB
#define SMEM_TOTAL 97792u

__device__ __forceinline__ uint32_t smem_u32(const void* p) {
    uint32_t a;
    asm("{ .reg .u64 t; cvta.to.shared.u64 t, %1; cvt.u32.u64 %0, t; }"
        : "=r"(a) : "l"(p));
    return a;
}

__device__ __forceinline__ void mma_f16(float* c, const uint32_t* a,
                                        uint32_t b0, uint32_t b1) {
    asm volatile(
        "mma.sync.aligned.m16n8k16.row.col.f32.f16.f16.f32 "
        "{%0,%1,%2,%3}, {%4,%5,%6,%7}, {%8,%9}, {%0,%1,%2,%3};"
        : "+f"(c[0]), "+f"(c[1]), "+f"(c[2]), "+f"(c[3])
        : "r"(a[0]), "r"(a[1]), "r"(a[2]), "r"(a[3]), "r"(b0), "r"(b1));
}

__device__ __forceinline__ void ldsm4(uint32_t* r, uint32_t addr) {
    asm volatile("ldmatrix.sync.aligned.m8n8.x4.shared.b16 {%0,%1,%2,%3}, [%4];"
                 : "=r"(r[0]), "=r"(r[1]), "=r"(r[2]), "=r"(r[3]) : "r"(addr));
}

// pack (lo element, hi element) -> fp16x2  (lo in low 16 bits)
__device__ __forceinline__ uint32_t packh(float lo, float hi) {
    __half2 h = __floats2half2_rn(lo, hi);
    return *reinterpret_cast<uint32_t*>(&h);
}

// GEMM1: acc[16][4] += X[16,64] @ W1   (64 MMAs, 32 LDSM.x4)
__device__ __forceinline__ void gemm1(float (&acc)[16][4],
    const uint32_t (&xh)[4][4], uint32_t base)
{
    #pragma unroll
    for (int kk = 0; kk < 4; kk++) {
        #pragma unroll
        for (int t2 = 0; t2 < 8; t2++) {
            uint32_t addr = base + (uint32_t)t2 * (16u * P1) + (uint32_t)kk * 32u;
            uint32_t b[4]; ldsm4(b, addr);
            mma_f16(acc[2*t2],   xh[kk], b[0], b[1]);
            mma_f16(acc[2*t2+1], xh[kk], b[2], b[3]);
        }
    }
}

// GEMM2: acc[8][4] += H[16,128] @ W2   (64 MMAs, 32 LDSM.x4)
__device__ __forceinline__ void gemm2(float (&acc)[8][4],
    const uint32_t (&Hh)[16][2], uint32_t base)
{
    #pragma unroll
    for (int kk = 0; kk < 8; kk++) {
        uint32_t a[4] = {Hh[2*kk][0], Hh[2*kk][1], Hh[2*kk+1][0], Hh[2*kk+1][1]};
        #pragma unroll
        for (int g2 = 0; g2 < 4; g2++) {
            uint32_t addr = base + (uint32_t)g2 * (16u * P2) + (uint32_t)kk * 32u;
            uint32_t b[4]; ldsm4(b, addr);
            mma_f16(acc[2*g2],   a, b[0], b[1]);
            mma_f16(acc[2*g2+1], a, b[2], b[3]);
        }
    }
}

__device__ __forceinline__ void tanh_pack(const float (&acc)[16][4],
    const float* bias_sm, int cpair, uint32_t (&Hh)[16][2])
{
    #pragma unroll
    for (int t = 0; t < 16; t++) {
        float b0 = bias_sm[8*t + cpair];
        float b1 = bias_sm[8*t + cpair + 1];
        Hh[t][0] = packh(tanhf(acc[t][0] + b0), tanhf(acc[t][1] + b1));
        Hh[t][1] = packh(tanhf(acc[t][2] + b0), tanhf(acc[t][3] + b1));
    }
}

__device__ __forceinline__ void pack_frags(const float (&x)[8][4],
    uint32_t (&xh)[4][4])
{
    #pragma unroll
    for (int kk = 0; kk < 4; kk++) {
        xh[kk][0] = packh(x[2*kk][0],   x[2*kk][1]);
        xh[kk][1] = packh(x[2*kk][2],   x[2*kk][3]);
        xh[kk][2] = packh(x[2*kk+1][0], x[2*kk+1][1]);
        xh[kk][3] = packh(x[2*kk+1][2], x[2*kk+1][3]);
    }
}

__global__ void __launch_bounds__(THREADS, 1)
sde_fp16_kernel(const float* __restrict__ x0,
                const float* __restrict__ noise,
                const float* __restrict__ Wd1, const float* __restrict__ bd1,
                const float* __restrict__ Wd2, const float* __restrict__ bd2,
                const float* __restrict__ Wg1, const float* __restrict__ bg1,
                const float* __restrict__ Wg2, const float* __restrict__ bg2,
                float* __restrict__ out)
{
    extern __shared__ char smc[];
    const uint32_t smem_base = smem_u32(smc);
    const int tid = threadIdx.x;

    // ---- stage weights (fp16, transposed [n][k], padded pitch) ----
    for (int idx = tid; idx < DIM * HID; idx += THREADS) {     // W1: [64 k][128 n]
        int k = idx >> 7, n = idx & 127;
        *(__half*)(smc + W1D_OFF + (uint32_t)n * P1 + 2*k) = __float2half_rn(Wd1[idx]);
        *(__half*)(smc + W1G_OFF + (uint32_t)n * P1 + 2*k) = __float2half_rn(Wg1[idx]);
    }
    for (int idx = tid; idx < HID * DIM; idx += THREADS) {     // W2: [128 k][64 n]
        int k = idx >> 6, n = idx & 63;
        *(__half*)(smc + W2D_OFF + (uint32_t)n * P2 + 2*k) = __float2half_rn(Wd2[idx]);
        *(__half*)(smc + W2G_OFF + (uint32_t)n * P2 + 2*k) = __float2half_rn(Wg2[idx]);
    }
    for (int i = tid; i < HID; i += THREADS) {
        ((float*)(smc + B1D_OFF))[i] = bd1[i];
        ((float*)(smc + B1G_OFF))[i] = bg1[i];
    }
    for (int i = tid; i < DIM; i += THREADS) {
        ((float*)(smc + B2D_OFF))[i] = bd2[i];
        ((float*)(smc + B2G_OFF))[i] = bg2[i];
    }
    __syncthreads();

    const int wid  = tid >> 5, lane = tid & 31;
    const int tile = wid & 3;              // warp pair (tile, tile+4) on SMSP 'tile'
    const bool isF = (wid < 4);            // drift/update warp vs diffusion warp
    const int g = lane >> 2;
    const int cpair = (lane & 3) * 2;
    const int row0 = blockIdx.x * 64 + tile * 16 + g;
    const int barid = 1 + tile;

    // ldmatrix per-lane base address components
    const int rowA = (lane & 7) + ((lane >> 4) << 3);
    const uint32_t colo = (uint32_t)((lane >> 3) & 1) * 16u;
    const uint32_t g1 = smem_base + (isF ? W1D_OFF : W1G_OFF) + (uint32_t)rowA * P1 + colo;
    const uint32_t g2 = smem_base + (isF ? W2D_OFF : W2G_OFF) + (uint32_t)rowA * P2 + colo;

    const float* sb1  = (const float*)(smc + (isF ? B1D_OFF : B1G_OFF));
    const float* sb2d = (const float*)(smc + B2D_OFF);
    const float* sb2g = (const float*)(smc + B2G_OFF);

    // exchange buffers (lane-to-lane, conflict-free 16B/lane)
    char* xfp = smc + XFRAG_OFF + (uint32_t)tile * 2048u + (uint32_t)lane * 16u;
    char* gxp = smc + GEX_OFF   + (uint32_t)tile * 4096u + (uint32_t)lane * 16u;

    // ---- init: both warps load x0, pack frags; f-warp keeps x + writes out[0]
    float x[8][4];
    uint32_t xh[4][4];
    #pragma unroll
    for (int t = 0; t < 8; t++) {
        float2 v0 = *(const float2*)(x0 + (size_t)row0 * DIM + 8*t + cpair);
        float2 v1 = *(const float2*)(x0 + (size_t)(row0 + 8) * DIM + 8*t + cpair);
        x[t][0] = v0.x; x[t][1] = v0.y; x[t][2] = v1.x; x[t][3] = v1.y;
        if (isF) {
            *(float2*)(out + (size_t)row0 * DIM + 8*t + cpair) = v0;
            *(float2*)(out + (size_t)(row0 + 8) * DIM + 8*t + cpair) = v1;
        }
    }
    pack_frags(x, xh);

    const float DTC = 0.01f;
    const float SDT = 0.1f;

    #pragma unroll 1
    for (int step = 0; step < NSTEPS; ++step) {
        float nz[8][4];
        if (isF) {   // prefetch noise early: LDG overlaps the GEMMs
            const float* nb = noise + (size_t)step * BATCH * DIM;
            #pragma unroll
            for (int t = 0; t < 8; t++) {
                float2 v0 = *(const float2*)(nb + (size_t)row0 * DIM + 8*t + cpair);
                float2 v1 = *(const float2*)(nb + (size_t)(row0 + 8) * DIM + 8*t + cpair);
                nz[t][0] = v0.x * SDT; nz[t][1] = v0.y * SDT;
                nz[t][2] = v1.x * SDT; nz[t][3] = v1.y * SDT;
            }
        }

        // ---- own MLP: GEMM1 -> tanh -> GEMM2 ----
        float acc1[16][4];
        #pragma unroll
        for (int t = 0; t < 16; t++) { acc1[t][0]=0.f; acc1[t][1]=0.f; acc1[t][2]=0.f; acc1[t][3]=0.f; }
        gemm1(acc1, xh, g1);

        uint32_t Hh[16][2];
        tanh_pack(acc1, sb1, cpair, Hh);

        float a2[8][4];
        #pragma unroll
        for (int t = 0; t < 8; t++) { a2[t][0]=0.f; a2[t][1]=0.f; a2[t][2]=0.f; a2[t][3]=0.f; }
        gemm2(a2, Hh, g2);

        if (!isF) {
            // diffusion warp: publish g (+bias), then fetch next-step x frags
            #pragma unroll
            for (int t = 0; t < 8; t++) {
                float b0 = sb2g[8*t + cpair], b1 = sb2g[8*t + cpair + 1];
                float4 v = make_float4(a2[t][0] + b0, a2[t][1] + b1,
                                       a2[t][2] + b0, a2[t][3] + b1);
                *(float4*)(gxp + t * 512) = v;
            }
            asm volatile("bar.sync %0, %1;" :: "r"(barid), "n"(64) : "memory");
            asm volatile("bar.sync %0, %1;" :: "r"(barid), "n"(64) : "memory");
            #pragma unroll
            for (int kk = 0; kk < 4; kk++) {
                uint4 vh = *(uint4*)(xfp + kk * 512);
                xh[kk][0] = vh.x; xh[kk][1] = vh.y; xh[kk][2] = vh.z; xh[kk][3] = vh.w;
            }
        } else {
            // drift warp: wait for g, Euler-Maruyama update, publish new x frags
            asm volatile("bar.sync %0, %1;" :: "r"(barid), "n"(64) : "memory");
            float* ob = out + (size_t)(step + 1) * BATCH * DIM;
            #pragma unroll
            for (int t = 0; t < 8; t++) {
                float4 gv = *(const float4*)(gxp + t * 512);
                float bd0 = sb2d[8*t + cpair], bd1v = sb2d[8*t + cpair + 1];
                x[t][0] = fmaf(gv.x, nz[t][0], fmaf(a2[t][0] + bd0,  DTC, x[t][0]));
                x[t][1] = fmaf(gv.y, nz[t][1], fmaf(a2[t][1] + bd1v, DTC, x[t][1]));
                x[t][2] = fmaf(gv.z, nz[t][2], fmaf(a2[t][2] + bd0,  DTC, x[t][2]));
                x[t][3] = fmaf(gv.w, nz[t][3], fmaf(a2[t][3] + bd1v, DTC, x[t][3]));
                *(float2*)(ob + (size_t)row0 * DIM + 8*t + cpair)       = make_float2(x[t][0], x[t][1]);
                *(float2*)(ob + (size_t)(row0 + 8) * DIM + 8*t + cpair) = make_float2(x[t][2], x[t][3]);
            }
            pack_frags(x, xh);
            #pragma unroll
            for (int kk = 0; kk < 4; kk++)
                *(uint4*)(xfp + kk * 512) = make_uint4(xh[kk][0], xh[kk][1], xh[kk][2], xh[kk][3]);
            asm volatile("bar.sync %0, %1;" :: "r"(barid), "n"(64) : "memory");
        }
    }
}

extern "C" void kernel_launch(void* const* d_in, const int* in_sizes, int n_in,
                              void* d_out, int out_size)
{
    const float* x0    = (const float*)d_in[0];
    const float* noise = (const float*)d_in[2];
    const float* Wd1   = (const float*)d_in[3];
    const float* bd1   = (const float*)d_in[4];
    const float* Wd2   = (const float*)d_in[5];
    const float* bd2   = (const float*)d_in[6];
    const float* Wg1   = (const float*)d_in[7];
    const float* bg1   = (const float*)d_in[8];
    const float* Wg2   = (const float*)d_in[9];
    const float* bg2   = (const float*)d_in[10];
    float* out = (float*)d_out;

    cudaFuncSetAttribute(sde_fp16_kernel,
                         cudaFuncAttributeMaxDynamicSharedMemorySize, SMEM_TOTAL);
    sde_fp16_kernel<<<NBLK, THREADS, SMEM_TOTAL>>>(
        x0, noise, Wd1, bd1, Wd2, bd2, Wg1, bg1, Wg2, bg2, out);
}

// round 8
// speedup vs baseline: 28.1406x; 1.1964x over previous
#include <cuda_runtime.h>
#include <cuda_fp16.h>
#include <cstdint>

#define BATCH   8192
#define DIM     64
#define HID     128
#define NSTEPS  100
#define THREADS 256
#define NBLK    128

// ---- smem layout (bytes) ----
#define P1 144u   // W1^T row pitch: 64 fp16 = 128B + 16B pad
#define P2 272u   // W2^T row pitch: 128 fp16 = 256B + 16B pad
#define W1D_OFF 0u
#define W1G_OFF 18432u       // 128*144
#define W2D_OFF 36864u
#define W2G_OFF 54272u       // + 64*272
#define B1D_OFF 71680u
#define B1G_OFF 72192u
#define B2D_OFF 72704u
#define B2G_OFF 72960u
#define XFRAG_OFF 73216u     // [4 tiles][4 kk][32 lanes][16B] = 8KB
#define GEX_OFF   81408u     // [4 tiles][8 t][32 lanes][16B] = 16KB
#define SMEM_TOTAL 97792u

__device__ __forceinline__ uint32_t smem_u32(const void* p) {
    uint32_t a;
    asm("{ .reg .u64 t; cvta.to.shared.u64 t, %1; cvt.u32.u64 %0, t; }"
        : "=r"(a) : "l"(p));
    return a;
}

__device__ __forceinline__ float tanh_fast(float v) {
    float r;
    asm("tanh.approx.f32 %0, %1;" : "=f"(r) : "f"(v));
    return r;
}

__device__ __forceinline__ void mma_f16(float* c, const uint32_t* a,
                                        uint32_t b0, uint32_t b1) {
    asm volatile(
        "mma.sync.aligned.m16n8k16.row.col.f32.f16.f16.f32 "
        "{%0,%1,%2,%3}, {%4,%5,%6,%7}, {%8,%9}, {%0,%1,%2,%3};"
        : "+f"(c[0]), "+f"(c[1]), "+f"(c[2]), "+f"(c[3])
        : "r"(a[0]), "r"(a[1]), "r"(a[2]), "r"(a[3]), "r"(b0), "r"(b1));
}

__device__ __forceinline__ void ldsm4(uint32_t* r, uint32_t addr) {
    asm volatile("ldmatrix.sync.aligned.m8n8.x4.shared.b16 {%0,%1,%2,%3}, [%4];"
                 : "=r"(r[0]), "=r"(r[1]), "=r"(r[2]), "=r"(r[3]) : "r"(addr));
}

// pack (lo element, hi element) -> fp16x2  (lo in low 16 bits)
__device__ __forceinline__ uint32_t packh(float lo, float hi) {
    __half2 h = __floats2half2_rn(lo, hi);
    return *reinterpret_cast<uint32_t*>(&h);
}

// GEMM1: acc[16][4] += X[16,64] @ W1   (64 MMAs, 32 LDSM.x4)
__device__ __forceinline__ void gemm1(float (&acc)[16][4],
    const uint32_t (&xh)[4][4], uint32_t base)
{
    #pragma unroll
    for (int kk = 0; kk < 4; kk++) {
        #pragma unroll
        for (int t2 = 0; t2 < 8; t2++) {
            uint32_t addr = base + (uint32_t)t2 * (16u * P1) + (uint32_t)kk * 32u;
            uint32_t b[4]; ldsm4(b, addr);
            mma_f16(acc[2*t2],   xh[kk], b[0], b[1]);
            mma_f16(acc[2*t2+1], xh[kk], b[2], b[3]);
        }
    }
}

// GEMM2: acc[8][4] += H[16,128] @ W2   (64 MMAs, 32 LDSM.x4)
__device__ __forceinline__ void gemm2(float (&acc)[8][4],
    const uint32_t (&Hh)[16][2], uint32_t base)
{
    #pragma unroll
    for (int kk = 0; kk < 8; kk++) {
        uint32_t a[4] = {Hh[2*kk][0], Hh[2*kk][1], Hh[2*kk+1][0], Hh[2*kk+1][1]};
        #pragma unroll
        for (int g2 = 0; g2 < 4; g2++) {
            uint32_t addr = base + (uint32_t)g2 * (16u * P2) + (uint32_t)kk * 32u;
            uint32_t b[4]; ldsm4(b, addr);
            mma_f16(acc[2*g2],   a, b[0], b[1]);
            mma_f16(acc[2*g2+1], a, b[2], b[3]);
        }
    }
}

__device__ __forceinline__ void tanh_pack(const float (&acc)[16][4],
    const float* bias_sm, int cpair, uint32_t (&Hh)[16][2])
{
    #pragma unroll
    for (int t = 0; t < 16; t++) {
        float b0 = bias_sm[8*t + cpair];
        float b1 = bias_sm[8*t + cpair + 1];
        Hh[t][0] = packh(tanh_fast(acc[t][0] + b0), tanh_fast(acc[t][1] + b1));
        Hh[t][1] = packh(tanh_fast(acc[t][2] + b0), tanh_fast(acc[t][3] + b1));
    }
}

__device__ __forceinline__ void pack_frags(const float (&x)[8][4],
    uint32_t (&xh)[4][4])
{
    #pragma unroll
    for (int kk = 0; kk < 4; kk++) {
        xh[kk][0] = packh(x[2*kk][0],   x[2*kk][1]);
        xh[kk][1] = packh(x[2*kk][2],   x[2*kk][3]);
        xh[kk][2] = packh(x[2*kk+1][0], x[2*kk+1][1]);
        xh[kk][3] = packh(x[2*kk+1][2], x[2*kk+1][3]);
    }
}

__global__ void __launch_bounds__(THREADS, 1)
sde_fp16_kernel(const float* __restrict__ x0,
                const float* __restrict__ noise,
                const float* __restrict__ Wd1, const float* __restrict__ bd1,
                const float* __restrict__ Wd2, const float* __restrict__ bd2,
                const float* __restrict__ Wg1, const float* __restrict__ bg1,
                const float* __restrict__ Wg2, const float* __restrict__ bg2,
                float* __restrict__ out)
{
    extern __shared__ char smc[];
    const uint32_t smem_base = smem_u32(smc);
    const int tid = threadIdx.x;

    // ---- stage weights (fp16, transposed [n][k], padded pitch) ----
    for (int idx = tid; idx < DIM * HID; idx += THREADS) {     // W1: [64 k][128 n]
        int k = idx >> 7, n = idx & 127;
        *(__half*)(smc + W1D_OFF + (uint32_t)n * P1 + 2*k) = __float2half_rn(Wd1[idx]);
        *(__half*)(smc + W1G_OFF + (uint32_t)n * P1 + 2*k) = __float2half_rn(Wg1[idx]);
    }
    for (int idx = tid; idx < HID * DIM; idx += THREADS) {     // W2: [128 k][64 n]
        int k = idx >> 6, n = idx & 63;
        *(__half*)(smc + W2D_OFF + (uint32_t)n * P2 + 2*k) = __float2half_rn(Wd2[idx]);
        *(__half*)(smc + W2G_OFF + (uint32_t)n * P2 + 2*k) = __float2half_rn(Wg2[idx]);
    }
    for (int i = tid; i < HID; i += THREADS) {
        ((float*)(smc + B1D_OFF))[i] = bd1[i];
        ((float*)(smc + B1G_OFF))[i] = bg1[i];
    }
    for (int i = tid; i < DIM; i += THREADS) {
        ((float*)(smc + B2D_OFF))[i] = bd2[i];
        ((float*)(smc + B2G_OFF))[i] = bg2[i];
    }
    __syncthreads();

    const int wid  = tid >> 5, lane = tid & 31;
    const int tile = wid & 3;              // warp pair (tile, tile+4) on SMSP 'tile'
    const bool isF = (wid < 4);            // drift/update warp vs diffusion/noise warp
    const int g = lane >> 2;
    const int cpair = (lane & 3) * 2;
    const int row0 = blockIdx.x * 64 + tile * 16 + g;
    const int barid = 1 + tile;

    // ldmatrix per-lane base address components
    const int rowA = (lane & 7) + ((lane >> 4) << 3);
    const uint32_t colo = (uint32_t)((lane >> 3) & 1) * 16u;
    const uint32_t g1 = smem_base + (isF ? W1D_OFF : W1G_OFF) + (uint32_t)rowA * P1 + colo;
    const uint32_t g2 = smem_base + (isF ? W2D_OFF : W2G_OFF) + (uint32_t)rowA * P2 + colo;

    const float* sb1  = (const float*)(smc + (isF ? B1D_OFF : B1G_OFF));
    const float* sb2d = (const float*)(smc + B2D_OFF);
    const float* sb2g = (const float*)(smc + B2G_OFF);

    // exchange buffers (lane-to-lane, conflict-free 16B/lane)
    char* xfp = smc + XFRAG_OFF + (uint32_t)tile * 2048u + (uint32_t)lane * 16u;
    char* gxp = smc + GEX_OFF   + (uint32_t)tile * 4096u + (uint32_t)lane * 16u;

    // ---- init: both warps load x0, pack frags; f-warp keeps x + writes out[0]
    float x[8][4];
    uint32_t xh[4][4];
    #pragma unroll
    for (int t = 0; t < 8; t++) {
        float2 v0 = *(const float2*)(x0 + (size_t)row0 * DIM + 8*t + cpair);
        float2 v1 = *(const float2*)(x0 + (size_t)(row0 + 8) * DIM + 8*t + cpair);
        x[t][0] = v0.x; x[t][1] = v0.y; x[t][2] = v1.x; x[t][3] = v1.y;
        if (isF) {
            *(float2*)(out + (size_t)row0 * DIM + 8*t + cpair) = v0;
            *(float2*)(out + (size_t)(row0 + 8) * DIM + 8*t + cpair) = v1;
        }
    }
    pack_frags(x, xh);

    const float DTC = 0.01f;
    const float SDT = 0.1f;

    #pragma unroll 1
    for (int step = 0; step < NSTEPS; ++step) {
        float nz[8][4];
        if (!isF) {   // g-warp owns the noise: LDG overlaps its GEMMs
            const float* nb = noise + (size_t)step * BATCH * DIM;
            #pragma unroll
            for (int t = 0; t < 8; t++) {
                float2 v0 = *(const float2*)(nb + (size_t)row0 * DIM + 8*t + cpair);
                float2 v1 = *(const float2*)(nb + (size_t)(row0 + 8) * DIM + 8*t + cpair);
                nz[t][0] = v0.x * SDT; nz[t][1] = v0.y * SDT;
                nz[t][2] = v1.x * SDT; nz[t][3] = v1.y * SDT;
            }
        }

        // ---- own MLP: GEMM1 -> tanh -> GEMM2 ----
        float acc1[16][4];
        #pragma unroll
        for (int t = 0; t < 16; t++) { acc1[t][0]=0.f; acc1[t][1]=0.f; acc1[t][2]=0.f; acc1[t][3]=0.f; }
        gemm1(acc1, xh, g1);

        uint32_t Hh[16][2];
        tanh_pack(acc1, sb1, cpair, Hh);

        float a2[8][4];
        #pragma unroll
        for (int t = 0; t < 8; t++) { a2[t][0]=0.f; a2[t][1]=0.f; a2[t][2]=0.f; a2[t][3]=0.f; }
        gemm2(a2, Hh, g2);

        if (!isF) {
            // g-warp: publish (g + bias) * (dw*sqrt_dt), then fetch next-step x frags
            #pragma unroll
            for (int t = 0; t < 8; t++) {
                float b0 = sb2g[8*t + cpair], b1 = sb2g[8*t + cpair + 1];
                float4 v = make_float4((a2[t][0] + b0) * nz[t][0],
                                       (a2[t][1] + b1) * nz[t][1],
                                       (a2[t][2] + b0) * nz[t][2],
                                       (a2[t][3] + b1) * nz[t][3]);
                *(float4*)(gxp + t * 512) = v;
            }
            asm volatile("bar.sync %0, %1;" :: "r"(barid), "n"(64) : "memory");
            asm volatile("bar.sync %0, %1;" :: "r"(barid), "n"(64) : "memory");
            #pragma unroll
            for (int kk = 0; kk < 4; kk++) {
                uint4 vh = *(uint4*)(xfp + kk * 512);
                xh[kk][0] = vh.x; xh[kk][1] = vh.y; xh[kk][2] = vh.z; xh[kk][3] = vh.w;
            }
        } else {
            // f-warp: wait for g*dw, Euler-Maruyama update, publish new x frags
            asm volatile("bar.sync %0, %1;" :: "r"(barid), "n"(64) : "memory");
            float* ob = out + (size_t)(step + 1) * BATCH * DIM;
            #pragma unroll
            for (int t = 0; t < 8; t++) {
                float4 gv = *(const float4*)(gxp + t * 512);
                float bd0 = sb2d[8*t + cpair], bd1v = sb2d[8*t + cpair + 1];
                x[t][0] = fmaf(a2[t][0] + bd0,  DTC, x[t][0]) + gv.x;
                x[t][1] = fmaf(a2[t][1] + bd1v, DTC, x[t][1]) + gv.y;
                x[t][2] = fmaf(a2[t][2] + bd0,  DTC, x[t][2]) + gv.z;
                x[t][3] = fmaf(a2[t][3] + bd1v, DTC, x[t][3]) + gv.w;
                *(float2*)(ob + (size_t)row0 * DIM + 8*t + cpair)       = make_float2(x[t][0], x[t][1]);
                *(float2*)(ob + (size_t)(row0 + 8) * DIM + 8*t + cpair) = make_float2(x[t][2], x[t][3]);
            }
            pack_frags(x, xh);
            #pragma unroll
            for (int kk = 0; kk < 4; kk++)
                *(uint4*)(xfp + kk * 512) = make_uint4(xh[kk][0], xh[kk][1], xh[kk][2], xh[kk][3]);
            asm volatile("bar.sync %0, %1;" :: "r"(barid), "n"(64) : "memory");
        }
    }
}

extern "C" void kernel_launch(void* const* d_in, const int* in_sizes, int n_in,
                              void* d_out, int out_size)
{
    const float* x0    = (const float*)d_in[0];
    const float* noise = (const float*)d_in[2];
    const float* Wd1   = (const float*)d_in[3];
    const float* bd1   = (const float*)d_in[4];
    const float* Wd2   = (const float*)d_in[5];
    const float* bd2   = (const float*)d_in[6];
    const float* Wg1   = (const float*)d_in[7];
    const float* bg1   = (const float*)d_in[8];
    const float* Wg2   = (const float*)d_in[9];
    const float* bg2   = (const float*)d_in[10];
    float* out = (float*)d_out;

    cudaFuncSetAttribute(sde_fp16_kernel,
                         cudaFuncAttributeMaxDynamicSharedMemorySize, SMEM_TOTAL);
    sde_fp16_kernel<<<NBLK, THREADS, SMEM_TOTAL>>>(
        x0, noise, Wd1, bd1, Wd2, bd2, Wg1, bg1, Wg2, bg2, out);
}